// round 12
// baseline (speedup 1.0000x reference)
#include <cuda_runtime.h>
#include <cuda_bf16.h>
#include <math.h>
#include <stdint.h>

// ---------------------------------------------------------------- constants
#define B_      4096
#define N_      8192              // 2B rows
#define C_      128               // feature dim
#define MT      128               // rows per CTA stripe
#define NT      128               // cols per j-tile
#define TT      32                // tiles per j-half (4096/128)
#define THREADS 512
#define PITCH   144               // smem row pitch (128B int8 data + 16B pad)
#define LOG2E2  2.8853900817779268f   // 2*log2(e)  (= (1/T)*log2 e, T=0.5)
#define LN2     0.6931471805599453f
#define QS      127.0f
// dequant * softmax scale: (2*log2e) / 127^2
#define CSC     (LOG2E2 / (QS * QS))

// scratch (__device__ globals: allocation-free)
__device__ int8_t g_RQ[N_ * C_];          // normalized reps quantized s8 (x127)
__device__ float  g_rowsum[N_];           // sum_j exp(2*sim_ij), diag excluded
__device__ float  g_pos[N_];              // LOG2E2 * sim(i, (i+B) mod N)

// ---------------------------------------------------------------- helpers
__device__ __forceinline__ uint32_t smem_u32(const void* p) {
    uint32_t a;
    asm("{ .reg .u64 t; cvta.to.shared.u64 t, %1; cvt.u32.u64 %0, t; }"
        : "=r"(a) : "l"(p));
    return a;
}

__device__ __forceinline__ void ldsm_x4(uint32_t (&r)[4], uint32_t addr) {
    asm volatile("ldmatrix.sync.aligned.m8n8.x4.shared.b16 {%0,%1,%2,%3}, [%4];"
                 : "=r"(r[0]), "=r"(r[1]), "=r"(r[2]), "=r"(r[3]) : "r"(addr));
}

// s8 IMMA: m16n8k32, s32 accum. Fragment bytes identical to bf16 k16 layout,
// so ldmatrix.b16 addressing carries over unchanged.
__device__ __forceinline__ void mma16832_s8(int (&d)[4], const uint32_t* a,
                                            uint32_t b0, uint32_t b1) {
    asm volatile(
        "mma.sync.aligned.m16n8k32.row.col.s32.s8.s8.s32 "
        "{%0,%1,%2,%3}, {%4,%5,%6,%7}, {%8,%9}, {%0,%1,%2,%3};"
        : "+r"(d[0]), "+r"(d[1]), "+r"(d[2]), "+r"(d[3])
        : "r"(a[0]), "r"(a[1]), "r"(a[2]), "r"(a[3]), "r"(b0), "r"(b1));
}

__device__ __forceinline__ float ex2(float x) {
    float r;
    asm("ex2.approx.f32 %0, %1;" : "=f"(r) : "f"(x));
    return r;
}

#define CP_ASYNC16(saddr, gptr) \
    asm volatile("cp.async.cg.shared.global [%0], [%1], 16;" \
                 :: "r"(saddr), "l"(gptr))
#define CP_COMMIT()  asm volatile("cp.async.commit_group;" ::: "memory")
#define CP_WAIT0()   asm volatile("cp.async.wait_group 0;" ::: "memory")

// ---------------------------------------------------------------- kernel 1
// L2-normalize rows of [z_i; z_j], quantize to s8 (x127). One warp per row.
// Each lane owns 4 consecutive features -> packs one uint32.
__global__ void __launch_bounds__(256) normalize_kernel(
    const float* __restrict__ zi, const float* __restrict__ zj)
{
    const int w = threadIdx.x >> 5, lane = threadIdx.x & 31;
    const int row = blockIdx.x * 8 + w;
    const float* src = (row < B_) ? (zi + (size_t)row * C_)
                                  : (zj + (size_t)(row - B_) * C_);
    float4 v = ((const float4*)src)[lane];
    float ss = v.x * v.x + v.y * v.y + v.z * v.z + v.w * v.w;
    #pragma unroll
    for (int o = 16; o; o >>= 1) ss += __shfl_xor_sync(0xffffffffu, ss, o);
    const float q = rsqrtf(ss) * QS;

    const int q0 = __float2int_rn(v.x * q);
    const int q1 = __float2int_rn(v.y * q);
    const int q2 = __float2int_rn(v.z * q);
    const int q3 = __float2int_rn(v.w * q);
    const uint32_t pk = (uint32_t)(q0 & 0xFF) | ((uint32_t)(q1 & 0xFF) << 8) |
                        ((uint32_t)(q2 & 0xFF) << 16) | ((uint32_t)(q3 & 0xFF) << 24);
    ((uint32_t*)(g_RQ + (size_t)row * C_))[lane] = pk;

    if (blockIdx.x < 32) g_rowsum[blockIdx.x * 256 + threadIdx.x] = 0.f;
}

// ---------------------------------------------------------------- kernel 2
// Fused sim-GEMM (IMMA s8, k32) + exp-rowsum epilogue.
// 16 warps, 4(m) x 4(n), warp tile 32x32. A fragments persist in registers
// (32 regs); B tiles (16KB each) double-buffered via cp.async.
extern "C" __global__ void __launch_bounds__(THREADS, 1) ntxent_mma_kernel()
{
    extern __shared__ char smraw[];
    const uint32_t sA32 = smem_u32(smraw);
    const uint32_t sB32 = sA32 + MT * PITCH;

    const int tid  = threadIdx.x;
    const int lane = tid & 31, w = tid >> 5;
    const int wm = w & 3, wn = w >> 2;               // 4 x 4 warp grid
    const int ibase  = (blockIdx.x >> 1) * MT;
    const int jh     = blockIdx.x & 1;
    const int jhbase = jh * 4096;
    const int iw     = ibase + wm * 32;              // warp's 32-row window
    const int pw     = (iw + B_) & (N_ - 1);         // positive-col window

    // copy slots: tile = 128 rows x 8 chunks(16B) = 1024; 512 thr -> 2 passes
    const int cm = tid >> 3, cq = tid & 7;           // rows 0..63(+64p), chunk

    // prologue: A stripe (plain stores) + B tile 0 (cp.async), both from g_RQ
    #pragma unroll
    for (int p = 0; p < 2; p++) {
        const int m = p * 64 + cm;
        *(float4*)(smraw + m * PITCH + cq * 16) =
            *(const float4*)(g_RQ + (size_t)(ibase + m) * C_ + cq * 16);
        CP_ASYNC16(sB32 + (uint32_t)(m * PITCH + cq * 16),
                   g_RQ + (size_t)(jhbase + m) * C_ + cq * 16);
    }
    CP_COMMIT();
    CP_WAIT0();
    __syncthreads();

    // persistent A fragments: [ks][mf][4]  (32 regs), k32 per step, 4 steps
    const int lrow = lane & 15;
    const int lkb  = (lane >> 4) * 16;
    const uint32_t aAddr = sA32 + (uint32_t)((wm * 32 + lrow) * PITCH + lkb);
    uint32_t aReg[4][2][4];
    #pragma unroll
    for (int ks = 0; ks < 4; ks++) {
        ldsm_x4(aReg[ks][0], aAddr + (uint32_t)(ks * 32));
        ldsm_x4(aReg[ks][1], aAddr + (uint32_t)(16 * PITCH + ks * 32));
    }

    const uint32_t bOffs = (uint32_t)((wn * 32 + lrow) * PITCH + lkb);
    float rs[4] = {0.f, 0.f, 0.f, 0.f};
    const int rquad = lane >> 2;
    const int cpair = (lane & 3) * 2;

    for (int t = 0; t < TT; t++) {
        const uint32_t bufR = sB32 + (uint32_t)((t & 1) * (MT * PITCH));

        // async prefetch of next B tile into the other buffer
        if (t + 1 < TT) {
            const uint32_t bufW = sB32 + (uint32_t)(((t + 1) & 1) * (MT * PITCH));
            const int gb = jhbase + (t + 1) * NT;
            #pragma unroll
            for (int p = 0; p < 2; p++) {
                const int m = p * 64 + cm;
                CP_ASYNC16(bufW + (uint32_t)(m * PITCH + cq * 16),
                           g_RQ + (size_t)(gb + m) * C_ + cq * 16);
            }
            CP_COMMIT();
        }

        int acc[2][4][4];
        #pragma unroll
        for (int mf = 0; mf < 2; mf++)
            #pragma unroll
            for (int nf = 0; nf < 4; nf++)
                #pragma unroll
                for (int e = 0; e < 4; e++) acc[mf][nf][e] = 0;

        #pragma unroll
        for (int ks = 0; ks < 4; ks++) {
            uint32_t b[2][4];
            ldsm_x4(b[0], bufR + bOffs + (uint32_t)(ks * 32));
            ldsm_x4(b[1], bufR + bOffs + (uint32_t)(16 * PITCH + ks * 32));
            #pragma unroll
            for (int mf = 0; mf < 2; mf++)
                #pragma unroll
                for (int nf = 0; nf < 4; nf++) {
                    const int n16 = nf >> 1, g = nf & 1;
                    mma16832_s8(acc[mf][nf], aReg[ks][mf], b[n16][g], b[n16][g + 2]);
                }
        }

        // fused epilogue: dequant (s32 -> f32 * CSC gives LOG2E2*sim) -> ex2
        const int jt = jhbase + t * NT + wn * 32;
        #pragma unroll
        for (int nf = 0; nf < 4; nf++) {
            const int jb = jt + nf * 8;
            const bool hd = (unsigned)(jb - iw) < 32u;   // diag hits this frag
            const bool hp = (unsigned)(jb - pw) < 32u;   // pos  hits this frag
            if (!hd && !hp) {
                #pragma unroll
                for (int mf = 0; mf < 2; mf++)
                    #pragma unroll
                    for (int e = 0; e < 4; e++)
                        rs[mf * 2 + (e >> 1)] += ex2((float)acc[mf][nf][e] * CSC);
            } else {
                #pragma unroll
                for (int mf = 0; mf < 2; mf++)
                    #pragma unroll
                    for (int e = 0; e < 4; e++) {
                        const int ie = iw + mf * 16 + rquad + ((e & 2) ? 8 : 0);
                        const int je = jb + cpair + (e & 1);
                        const float d = (float)acc[mf][nf][e] * CSC;
                        if (je == ((ie + B_) & (N_ - 1))) g_pos[ie] = d;
                        rs[mf * 2 + (e >> 1)] += (je == ie) ? 0.f : ex2(d);
                    }
            }
        }

        if (t + 1 < TT) CP_WAIT0();
        __syncthreads();
    }

    // reduce rowsums across the lane quad, then atomically merge partials
    #pragma unroll
    for (int r = 0; r < 4; r++) {
        rs[r] += __shfl_xor_sync(0xffffffffu, rs[r], 1);
        rs[r] += __shfl_xor_sync(0xffffffffu, rs[r], 2);
    }
    if ((lane & 3) == 0) {
        #pragma unroll
        for (int r = 0; r < 4; r++) {
            const int row = iw + rquad + (r & 1) * 8 + (r >> 1) * 16;
            atomicAdd(&g_rowsum[row], rs[r]);
        }
    }
}

// ---------------------------------------------------------------- kernel 3
// loss_i = log(rowsum_i + 2^ps_i) - ps_i*ln2   (ps = LOG2E2*pos)
__global__ void __launch_bounds__(1024) finalize_kernel(float* __restrict__ out)
{
    const int tid = threadIdx.x;
    float s = 0.f;
    #pragma unroll
    for (int r = tid; r < N_; r += 1024) {
        const float ps = g_pos[r];
        s += logf(g_rowsum[r] + ex2(ps)) - ps * LN2;
    }
    #pragma unroll
    for (int o = 16; o; o >>= 1) s += __shfl_xor_sync(0xffffffffu, s, o);
    __shared__ float sw[32];
    if ((tid & 31) == 0) sw[tid >> 5] = s;
    __syncthreads();
    if (tid < 32) {
        float v = sw[tid];
        #pragma unroll
        for (int o = 16; o; o >>= 1) v += __shfl_xor_sync(0xffffffffu, v, o);
        if (tid == 0) out[0] = v * (1.0f / (float)N_);
    }
}

// ---------------------------------------------------------------- launcher
extern "C" void kernel_launch(void* const* d_in, const int* in_sizes, int n_in,
                              void* d_out, int out_size)
{
    const float* zi = (const float*)d_in[0];
    const float* zj = (const float*)d_in[1];
    float* out = (float*)d_out;

    const int smem_bytes = 3 * MT * PITCH;   // A + 2x B buffers = 55296
    cudaFuncSetAttribute(ntxent_mma_kernel,
                         cudaFuncAttributeMaxDynamicSharedMemorySize, smem_bytes);

    normalize_kernel<<<N_ / 8, 256>>>(zi, zj);
    ntxent_mma_kernel<<<128, THREADS, smem_bytes>>>();
    finalize_kernel<<<1, 1024>>>(out);
}

// round 13
// speedup vs baseline: 2.2836x; 2.2836x over previous
#include <cuda_runtime.h>
#include <cuda_bf16.h>
#include <math.h>
#include <stdint.h>

// ---------------------------------------------------------------- constants
#define B_      4096
#define N_      8192              // 2B rows
#define C_      128               // feature dim
#define MT      128               // block tile (rows and cols)
#define NSTRIPE 64                // 8192 / 128
#define NPAIR   2080              // 64*65/2 upper-triangle block pairs
#define THREADS 512
#define PITCH   272               // smem row pitch (256B bf16 data + 16B pad)
#define LOG2E2  2.8853900817779268f   // 2*log2(e)  (= (1/T)*log2 e, T=0.5)
#define LN2     0.6931471805599453f

// scratch (__device__ globals: allocation-free)
__device__ __nv_bfloat16 g_RA[N_ * C_];   // normalized reps * LOG2E2 (A side)
__device__ __nv_bfloat16 g_RB[N_ * C_];   // normalized reps (B side)
__device__ float g_rowsum[N_];            // sum_j exp(2*sim_ij), diag excluded
__device__ float g_pos[N_];               // LOG2E2 * sim(i, (i+B) mod N)

// ---------------------------------------------------------------- helpers
__device__ __forceinline__ uint32_t smem_u32(const void* p) {
    uint32_t a;
    asm("{ .reg .u64 t; cvta.to.shared.u64 t, %1; cvt.u32.u64 %0, t; }"
        : "=r"(a) : "l"(p));
    return a;
}

__device__ __forceinline__ void ldsm_x4(uint32_t (&r)[4], uint32_t addr) {
    asm volatile("ldmatrix.sync.aligned.m8n8.x4.shared.b16 {%0,%1,%2,%3}, [%4];"
                 : "=r"(r[0]), "=r"(r[1]), "=r"(r[2]), "=r"(r[3]) : "r"(addr));
}

__device__ __forceinline__ void mma16816(float (&d)[4], const uint32_t* a,
                                         uint32_t b0, uint32_t b1) {
    asm volatile(
        "mma.sync.aligned.m16n8k16.row.col.f32.bf16.bf16.f32 "
        "{%0,%1,%2,%3}, {%4,%5,%6,%7}, {%8,%9}, {%0,%1,%2,%3};"
        : "+f"(d[0]), "+f"(d[1]), "+f"(d[2]), "+f"(d[3])
        : "r"(a[0]), "r"(a[1]), "r"(a[2]), "r"(a[3]), "r"(b0), "r"(b1));
}

__device__ __forceinline__ float ex2(float x) {
    float r;
    asm("ex2.approx.f32 %0, %1;" : "=f"(r) : "f"(x));
    return r;
}

#define CP_ASYNC16(saddr, gptr) \
    asm volatile("cp.async.cg.shared.global [%0], [%1], 16;" \
                 :: "r"(saddr), "l"(gptr))
#define CP_COMMIT()  asm volatile("cp.async.commit_group;" ::: "memory")
#define CP_WAIT0()   asm volatile("cp.async.wait_group 0;" ::: "memory")

// ---------------------------------------------------------------- kernel 1
// L2-normalize rows of [z_i; z_j]; bf16 scaled by LOG2E2 (A side) and
// unscaled (B side). Also zero g_rowsum.
__global__ void __launch_bounds__(256) normalize_kernel(
    const float* __restrict__ zi, const float* __restrict__ zj)
{
    const int w = threadIdx.x >> 5, lane = threadIdx.x & 31;
    const int row = blockIdx.x * 8 + w;
    const float* src = (row < B_) ? (zi + (size_t)row * C_)
                                  : (zj + (size_t)(row - B_) * C_);
    float4 v = ((const float4*)src)[lane];
    float ss = v.x * v.x + v.y * v.y + v.z * v.z + v.w * v.w;
    #pragma unroll
    for (int o = 16; o; o >>= 1) ss += __shfl_xor_sync(0xffffffffu, ss, o);
    const float rn  = rsqrtf(ss);
    const float rnA = rn * LOG2E2;

    __nv_bfloat162 b0 = __floats2bfloat162_rn(v.x * rn, v.y * rn);
    __nv_bfloat162 b1 = __floats2bfloat162_rn(v.z * rn, v.w * rn);
    uint2 pb = { *(uint32_t*)&b0, *(uint32_t*)&b1 };
    ((uint2*)(g_RB + (size_t)row * C_))[lane] = pb;

    __nv_bfloat162 a0 = __floats2bfloat162_rn(v.x * rnA, v.y * rnA);
    __nv_bfloat162 a1 = __floats2bfloat162_rn(v.z * rnA, v.w * rnA);
    uint2 pa = { *(uint32_t*)&a0, *(uint32_t*)&a1 };
    ((uint2*)(g_RA + (size_t)row * C_))[lane] = pa;

    if (blockIdx.x < 32) g_rowsum[blockIdx.x * 256 + threadIdx.x] = 0.f;
}

// ---------------------------------------------------------------- kernel 2
// Symmetric fused sim-GEMM: one CTA per upper-triangle 128x128 block pair
// (I <= J). Each exp value feeds BOTH row-sum i (register reduce) and
// row-sum j (quad-transposed shuffle reduce) -- halves MMA and MUFU work.
// 16 warps, 4(m) x 4(n), warp tile 32x32.
extern "C" __global__ void __launch_bounds__(THREADS, 1) ntxent_sym_kernel()
{
    extern __shared__ char smraw[];
    const uint32_t sA32 = smem_u32(smraw);
    const uint32_t sB32 = sA32 + MT * PITCH;

    const int tid  = threadIdx.x;
    const int lane = tid & 31, w = tid >> 5;
    const int wm = w & 3, wn = w >> 2;               // 4 x 4 warp grid

    // decode upper-triangle pair (I, J), I <= J
    int r = blockIdx.x, I = 0;
    while (r >= NSTRIPE - I) { r -= NSTRIPE - I; I++; }
    const int J = I + r;
    const bool diag = (I == J);
    const bool posT = (J == I + 32);                 // pos pairs live here
    const int ibase = I * MT, jbase = J * MT;

    // cooperative async load of both stripes (A scaled, B unscaled)
    const int cm = tid >> 4, cq = tid & 15;          // rows 0..31(+32p), 16B col
    #pragma unroll
    for (int p = 0; p < 4; p++) {
        const int m = p * 32 + cm;
        CP_ASYNC16(sA32 + (uint32_t)(m * PITCH + cq * 16),
                   g_RA + (size_t)(ibase + m) * C_ + cq * 8);
        CP_ASYNC16(sB32 + (uint32_t)(m * PITCH + cq * 16),
                   g_RB + (size_t)(jbase + m) * C_ + cq * 8);
    }
    CP_COMMIT();
    CP_WAIT0();
    __syncthreads();

    // MMA: warp tile 32x32, K=128 in 8 k16 steps
    const int lrow = lane & 15;
    const int lkb  = (lane >> 4) * 16;
    const uint32_t aAddr = sA32 + (uint32_t)((wm * 32 + lrow) * PITCH + lkb);
    const uint32_t bAddr = sB32 + (uint32_t)((wn * 32 + lrow) * PITCH + lkb);

    float acc[2][4][4];
    #pragma unroll
    for (int mf = 0; mf < 2; mf++)
        #pragma unroll
        for (int nf = 0; nf < 4; nf++)
            #pragma unroll
            for (int e = 0; e < 4; e++) acc[mf][nf][e] = 0.f;

    #pragma unroll
    for (int ks = 0; ks < 8; ks++) {
        uint32_t a[2][4], b[2][4];
        ldsm_x4(a[0], aAddr + (uint32_t)(ks * 32));
        ldsm_x4(a[1], aAddr + (uint32_t)(16 * PITCH + ks * 32));
        ldsm_x4(b[0], bAddr + (uint32_t)(ks * 32));
        ldsm_x4(b[1], bAddr + (uint32_t)(16 * PITCH + ks * 32));
        #pragma unroll
        for (int mf = 0; mf < 2; mf++)
            #pragma unroll
            for (int nf = 0; nf < 4; nf++) {
                const int n16 = nf >> 1, g = nf & 1;
                mma16816(acc[mf][nf], a[mf], b[n16][g], b[n16][g + 2]);
            }
    }

    // epilogue: exp once, feed row-side (i) and column-side (j) sums
    const int iw = ibase + wm * 32;
    const int jt = jbase + wn * 32;
    const int rquad = lane >> 2;
    const int cpair = (lane & 3) * 2;
    // diag/pos elements sit at equal intra-block offsets -> only wm==wn warps
    const bool special = (diag || posT) && (wm == wn);

    float rs[4] = {0.f, 0.f, 0.f, 0.f};
    float cs[4][2] = {{0.f,0.f},{0.f,0.f},{0.f,0.f},{0.f,0.f}};

    #pragma unroll
    for (int nf = 0; nf < 4; nf++) {
        if (!special) {
            #pragma unroll
            for (int mf = 0; mf < 2; mf++)
                #pragma unroll
                for (int e = 0; e < 4; e++) {
                    const float ex = ex2(acc[mf][nf][e]);
                    rs[mf * 2 + (e >> 1)] += ex;
                    cs[nf][e & 1] += ex;
                }
        } else {
            const int jb = jt + nf * 8;
            #pragma unroll
            for (int mf = 0; mf < 2; mf++)
                #pragma unroll
                for (int e = 0; e < 4; e++) {
                    const int ie = iw + mf * 16 + rquad + ((e & 2) ? 8 : 0);
                    const int je = jb + cpair + (e & 1);
                    const float d = acc[mf][nf][e];
                    if (posT && je == ie + B_) { g_pos[ie] = d; g_pos[je] = d; }
                    const float ex = (diag && je == ie) ? 0.f : ex2(d);
                    rs[mf * 2 + (e >> 1)] += ex;
                    cs[nf][e & 1] += ex;
                }
        }
    }

    // row-side: reduce across lane quad, atomically merge 4 rows
    #pragma unroll
    for (int q = 0; q < 4; q++) {
        rs[q] += __shfl_xor_sync(0xffffffffu, rs[q], 1);
        rs[q] += __shfl_xor_sync(0xffffffffu, rs[q], 2);
    }
    if ((lane & 3) == 0) {
        #pragma unroll
        for (int q = 0; q < 4; q++) {
            const int row = iw + rquad + (q & 1) * 8 + (q >> 1) * 16;
            atomicAdd(&g_rowsum[row], rs[q]);
        }
    }

    // column-side (off-diagonal only): reduce across rquad (lanes 4,8,16),
    // lanes 0-3 then hold per-column totals for their cpair columns
    if (!diag) {
        #pragma unroll
        for (int nf = 0; nf < 4; nf++)
            #pragma unroll
            for (int par = 0; par < 2; par++) {
                float v = cs[nf][par];
                v += __shfl_xor_sync(0xffffffffu, v, 4);
                v += __shfl_xor_sync(0xffffffffu, v, 8);
                v += __shfl_xor_sync(0xffffffffu, v, 16);
                if (lane < 4)
                    atomicAdd(&g_rowsum[jt + nf * 8 + cpair + par], v);
            }
    }
}

// ---------------------------------------------------------------- kernel 3
// loss_i = log(rowsum_i + 2^ps_i) - ps_i*ln2   (ps = LOG2E2*pos)
__global__ void __launch_bounds__(1024) finalize_kernel(float* __restrict__ out)
{
    const int tid = threadIdx.x;
    float s = 0.f;
    #pragma unroll
    for (int r = tid; r < N_; r += 1024) {
        const float ps = g_pos[r];
        s += logf(g_rowsum[r] + ex2(ps)) - ps * LN2;
    }
    #pragma unroll
    for (int o = 16; o; o >>= 1) s += __shfl_xor_sync(0xffffffffu, s, o);
    __shared__ float sw[32];
    if ((tid & 31) == 0) sw[tid >> 5] = s;
    __syncthreads();
    if (tid < 32) {
        float v = sw[tid];
        #pragma unroll
        for (int o = 16; o; o >>= 1) v += __shfl_xor_sync(0xffffffffu, v, o);
        if (tid == 0) out[0] = v * (1.0f / (float)N_);
    }
}

// ---------------------------------------------------------------- launcher
extern "C" void kernel_launch(void* const* d_in, const int* in_sizes, int n_in,
                              void* d_out, int out_size)
{
    const float* zi = (const float*)d_in[0];
    const float* zj = (const float*)d_in[1];
    float* out = (float*)d_out;

    const int smem_bytes = 2 * MT * PITCH;   // A + B stripes = 69632
    cudaFuncSetAttribute(ntxent_sym_kernel,
                         cudaFuncAttributeMaxDynamicSharedMemorySize, smem_bytes);

    normalize_kernel<<<N_ / 8, 256>>>(zi, zj);
    ntxent_sym_kernel<<<NPAIR, THREADS, smem_bytes>>>();
    finalize_kernel<<<1, 1024>>>(out);
}

// round 14
// speedup vs baseline: 2.5868x; 1.1327x over previous
#include <cuda_runtime.h>
#include <cuda_bf16.h>
#include <math.h>
#include <stdint.h>

// ---------------------------------------------------------------- constants
#define B_      4096
#define N_      8192              // 2B rows
#define C_      128               // feature dim
#define MT      128               // block tile (rows and cols)
#define NSTRIPE 64                // 8192 / 128
#define CH      7                 // J-tiles per CTA chunk
#define NCTA    325               // sum_I ceil((64-I)/7)
#define THREADS 512
#define PITCH   272               // smem row pitch (256B bf16 data + 16B pad)
#define LOG2E2  2.8853900817779268f   // 2*log2(e)  (= (1/T)*log2 e, T=0.5)
#define LN2     0.6931471805599453f

// scratch (__device__ globals: allocation-free)
__device__ __nv_bfloat16 g_RA[N_ * C_];   // normalized reps * LOG2E2 (A side)
__device__ __nv_bfloat16 g_RB[N_ * C_];   // normalized reps (B side)
__device__ float g_rowsum[N_];            // sum_j exp(2*sim_ij), diag excluded
__device__ float g_pos[N_];               // LOG2E2 * sim(i, (i+B) mod N)

// ---------------------------------------------------------------- helpers
__device__ __forceinline__ uint32_t smem_u32(const void* p) {
    uint32_t a;
    asm("{ .reg .u64 t; cvta.to.shared.u64 t, %1; cvt.u32.u64 %0, t; }"
        : "=r"(a) : "l"(p));
    return a;
}

__device__ __forceinline__ void ldsm_x4(uint32_t (&r)[4], uint32_t addr) {
    asm volatile("ldmatrix.sync.aligned.m8n8.x4.shared.b16 {%0,%1,%2,%3}, [%4];"
                 : "=r"(r[0]), "=r"(r[1]), "=r"(r[2]), "=r"(r[3]) : "r"(addr));
}

__device__ __forceinline__ void mma16816(float (&d)[4], const uint32_t* a,
                                         uint32_t b0, uint32_t b1) {
    asm volatile(
        "mma.sync.aligned.m16n8k16.row.col.f32.bf16.bf16.f32 "
        "{%0,%1,%2,%3}, {%4,%5,%6,%7}, {%8,%9}, {%0,%1,%2,%3};"
        : "+f"(d[0]), "+f"(d[1]), "+f"(d[2]), "+f"(d[3])
        : "r"(a[0]), "r"(a[1]), "r"(a[2]), "r"(a[3]), "r"(b0), "r"(b1));
}

__device__ __forceinline__ float ex2(float x) {
    float r;
    asm("ex2.approx.f32 %0, %1;" : "=f"(r) : "f"(x));
    return r;
}

#define CP_ASYNC16(saddr, gptr) \
    asm volatile("cp.async.cg.shared.global [%0], [%1], 16;" \
                 :: "r"(saddr), "l"(gptr))
#define CP_COMMIT()  asm volatile("cp.async.commit_group;" ::: "memory")
#define CP_WAIT0()   asm volatile("cp.async.wait_group 0;" ::: "memory")

// ---------------------------------------------------------------- kernel 1
__global__ void __launch_bounds__(256) normalize_kernel(
    const float* __restrict__ zi, const float* __restrict__ zj)
{
    const int w = threadIdx.x >> 5, lane = threadIdx.x & 31;
    const int row = blockIdx.x * 8 + w;
    const float* src = (row < B_) ? (zi + (size_t)row * C_)
                                  : (zj + (size_t)(row - B_) * C_);
    float4 v = ((const float4*)src)[lane];
    float ss = v.x * v.x + v.y * v.y + v.z * v.z + v.w * v.w;
    #pragma unroll
    for (int o = 16; o; o >>= 1) ss += __shfl_xor_sync(0xffffffffu, ss, o);
    const float rn  = rsqrtf(ss);
    const float rnA = rn * LOG2E2;

    __nv_bfloat162 b0 = __floats2bfloat162_rn(v.x * rn, v.y * rn);
    __nv_bfloat162 b1 = __floats2bfloat162_rn(v.z * rn, v.w * rn);
    uint2 pb = { *(uint32_t*)&b0, *(uint32_t*)&b1 };
    ((uint2*)(g_RB + (size_t)row * C_))[lane] = pb;

    __nv_bfloat162 a0 = __floats2bfloat162_rn(v.x * rnA, v.y * rnA);
    __nv_bfloat162 a1 = __floats2bfloat162_rn(v.z * rnA, v.w * rnA);
    uint2 pa = { *(uint32_t*)&a0, *(uint32_t*)&a1 };
    ((uint2*)(g_RA + (size_t)row * C_))[lane] = pa;

    if (blockIdx.x < 32) g_rowsum[blockIdx.x * 256 + threadIdx.x] = 0.f;
}

// ---------------------------------------------------------------- kernel 2
// Symmetric + pipelined: CTA = (stripe I, chunk of <=7 J-tiles, J >= I).
// A stripe persistent in register fragments; B tiles double-buffered via
// cp.async issued before the current tile's MMA+epilogue. Each exp feeds
// row-sum i (register accumulate across chunk) and row-sum j (shuffle+atomic).
extern "C" __global__ void __launch_bounds__(THREADS, 1) ntxent_sym_kernel()
{
    extern __shared__ char smraw[];
    const uint32_t sA32 = smem_u32(smraw);
    const uint32_t sB32 = sA32 + MT * PITCH;

    const int tid  = threadIdx.x;
    const int lane = tid & 31, w = tid >> 5;
    const int wm = w & 3, wn = w >> 2;               // 4 x 4 warp grid

    // decode (I, chunk) from blockIdx over variable chunks/stripe
    int rem = blockIdx.x, I = 0;
    while (rem >= (NSTRIPE - I + CH - 1) / CH) {
        rem -= (NSTRIPE - I + CH - 1) / CH;
        I++;
    }
    const int J0   = I + rem * CH;
    const int JEND = min(J0 + CH, NSTRIPE);
    const int ibase = I * MT;

    // prologue: A stripe + first B tile via cp.async
    const int cm = tid >> 4, cq = tid & 15;          // rows 0..31(+32p), 16B col
    #pragma unroll
    for (int p = 0; p < 4; p++) {
        const int m = p * 32 + cm;
        CP_ASYNC16(sA32 + (uint32_t)(m * PITCH + cq * 16),
                   g_RA + (size_t)(ibase + m) * C_ + cq * 8);
        CP_ASYNC16(sB32 + (uint32_t)(m * PITCH + cq * 16),
                   g_RB + (size_t)(J0 * MT + m) * C_ + cq * 8);
    }
    CP_COMMIT();
    CP_WAIT0();
    __syncthreads();

    // persistent A fragments (64 regs)
    const int lrow = lane & 15;
    const int lkb  = (lane >> 4) * 16;
    const uint32_t aAddr = sA32 + (uint32_t)((wm * 32 + lrow) * PITCH + lkb);
    uint32_t aReg[8][2][4];
    #pragma unroll
    for (int ks = 0; ks < 8; ks++) {
        ldsm_x4(aReg[ks][0], aAddr + (uint32_t)(ks * 32));
        ldsm_x4(aReg[ks][1], aAddr + (uint32_t)(16 * PITCH + ks * 32));
    }

    const uint32_t bOffs = (uint32_t)((wn * 32 + lrow) * PITCH + lkb);
    const int iw = ibase + wm * 32;
    const int rquad = lane >> 2;
    const int cpair = (lane & 3) * 2;

    float rs[4] = {0.f, 0.f, 0.f, 0.f};             // row sums, whole chunk

    for (int J = J0; J < JEND; J++) {
        const int t = J - J0;
        const uint32_t bufR = sB32 + (uint32_t)((t & 1) * (MT * PITCH));

        // prefetch next B tile under this tile's compute
        if (J + 1 < JEND) {
            const uint32_t bufW = sB32 + (uint32_t)(((t + 1) & 1) * (MT * PITCH));
            #pragma unroll
            for (int p = 0; p < 4; p++) {
                const int m = p * 32 + cm;
                CP_ASYNC16(bufW + (uint32_t)(m * PITCH + cq * 16),
                           g_RB + (size_t)((J + 1) * MT + m) * C_ + cq * 8);
            }
            CP_COMMIT();
        }

        float acc[2][4][4];
        #pragma unroll
        for (int mf = 0; mf < 2; mf++)
            #pragma unroll
            for (int nf = 0; nf < 4; nf++)
                #pragma unroll
                for (int e = 0; e < 4; e++) acc[mf][nf][e] = 0.f;

        #pragma unroll
        for (int ks = 0; ks < 8; ks++) {
            uint32_t b[2][4];
            ldsm_x4(b[0], bufR + bOffs + (uint32_t)(ks * 32));
            ldsm_x4(b[1], bufR + bOffs + (uint32_t)(16 * PITCH + ks * 32));
            #pragma unroll
            for (int mf = 0; mf < 2; mf++)
                #pragma unroll
                for (int nf = 0; nf < 4; nf++) {
                    const int n16 = nf >> 1, g = nf & 1;
                    mma16816(acc[mf][nf], aReg[ks][mf], b[n16][g], b[n16][g + 2]);
                }
        }

        // epilogue: exp once, feed row-side (i) and column-side (j) sums
        const bool diag = (J == I);
        const bool posT = (J == I + 32);
        const bool special = (diag || posT) && (wm == wn);
        const int jt = J * MT + wn * 32;

        float cs[4][2] = {{0.f,0.f},{0.f,0.f},{0.f,0.f},{0.f,0.f}};

        #pragma unroll
        for (int nf = 0; nf < 4; nf++) {
            if (!special) {
                #pragma unroll
                for (int mf = 0; mf < 2; mf++)
                    #pragma unroll
                    for (int e = 0; e < 4; e++) {
                        const float ex = ex2(acc[mf][nf][e]);
                        rs[mf * 2 + (e >> 1)] += ex;
                        cs[nf][e & 1] += ex;
                    }
            } else {
                const int jb = jt + nf * 8;
                #pragma unroll
                for (int mf = 0; mf < 2; mf++)
                    #pragma unroll
                    for (int e = 0; e < 4; e++) {
                        const int ie = iw + mf * 16 + rquad + ((e & 2) ? 8 : 0);
                        const int je = jb + cpair + (e & 1);
                        const float d = acc[mf][nf][e];
                        if (posT && je == ie + B_) { g_pos[ie] = d; g_pos[je] = d; }
                        const float ex = (diag && je == ie) ? 0.f : ex2(d);
                        rs[mf * 2 + (e >> 1)] += ex;
                        cs[nf][e & 1] += ex;
                    }
            }
        }

        // column-side (off-diagonal only): reduce across rquad, atomics
        if (!diag) {
            #pragma unroll
            for (int nf = 0; nf < 4; nf++)
                #pragma unroll
                for (int par = 0; par < 2; par++) {
                    float v = cs[nf][par];
                    v += __shfl_xor_sync(0xffffffffu, v, 4);
                    v += __shfl_xor_sync(0xffffffffu, v, 8);
                    v += __shfl_xor_sync(0xffffffffu, v, 16);
                    if (lane < 4)
                        atomicAdd(&g_rowsum[jt + nf * 8 + cpair + par], v);
                }
        }

        if (J + 1 < JEND) CP_WAIT0();
        __syncthreads();
    }

    // row-side: reduce across lane quad once per chunk, then atomics
    #pragma unroll
    for (int q = 0; q < 4; q++) {
        rs[q] += __shfl_xor_sync(0xffffffffu, rs[q], 1);
        rs[q] += __shfl_xor_sync(0xffffffffu, rs[q], 2);
    }
    if ((lane & 3) == 0) {
        #pragma unroll
        for (int q = 0; q < 4; q++) {
            const int row = iw + rquad + (q & 1) * 8 + (q >> 1) * 16;
            atomicAdd(&g_rowsum[row], rs[q]);
        }
    }
}

// ---------------------------------------------------------------- kernel 3
// loss_i = log(rowsum_i + 2^ps_i) - ps_i*ln2   (ps = LOG2E2*pos)
__global__ void __launch_bounds__(1024) finalize_kernel(float* __restrict__ out)
{
    const int tid = threadIdx.x;
    float s = 0.f;
    #pragma unroll
    for (int r = tid; r < N_; r += 1024) {
        const float ps = g_pos[r];
        s += logf(g_rowsum[r] + ex2(ps)) - ps * LN2;
    }
    #pragma unroll
    for (int o = 16; o; o >>= 1) s += __shfl_xor_sync(0xffffffffu, s, o);
    __shared__ float sw[32];
    if ((tid & 31) == 0) sw[tid >> 5] = s;
    __syncthreads();
    if (tid < 32) {
        float v = sw[tid];
        #pragma unroll
        for (int o = 16; o; o >>= 1) v += __shfl_xor_sync(0xffffffffu, v, o);
        if (tid == 0) out[0] = v * (1.0f / (float)N_);
    }
}

// ---------------------------------------------------------------- launcher
extern "C" void kernel_launch(void* const* d_in, const int* in_sizes, int n_in,
                              void* d_out, int out_size)
{
    const float* zi = (const float*)d_in[0];
    const float* zj = (const float*)d_in[1];
    float* out = (float*)d_out;

    const int smem_bytes = 3 * MT * PITCH;   // A + 2x B buffers = 104448
    cudaFuncSetAttribute(ntxent_sym_kernel,
                         cudaFuncAttributeMaxDynamicSharedMemorySize, smem_bytes);

    normalize_kernel<<<N_ / 8, 256>>>(zi, zj);
    ntxent_sym_kernel<<<NCTA, THREADS, smem_bytes>>>();
    finalize_kernel<<<1, 1024>>>(out);
}

// round 15
// speedup vs baseline: 2.8584x; 1.1050x over previous
#include <cuda_runtime.h>
#include <cuda_bf16.h>
#include <math.h>
#include <stdint.h>

// ---------------------------------------------------------------- constants
#define B_      4096
#define N_      8192              // 2B rows
#define C_      128               // feature dim
#define MT      128               // block tile (rows and cols)
#define NSTRIPE 64                // 8192 / 128
#define NTILE   2080              // 64*65/2 upper-triangle block pairs
#define NCTA    148               // one CTA per SM, single wave
#define THREADS 512
#define PITCH   272               // smem row pitch (256B bf16 data + 16B pad)
#define LOG2E2  2.8853900817779268f   // 2*log2(e)  (= (1/T)*log2 e, T=0.5)
#define LN2     0.6931471805599453f

// scratch (__device__ globals: allocation-free)
__device__ __nv_bfloat16 g_RA[N_ * C_];   // normalized reps * LOG2E2 (A side)
__device__ __nv_bfloat16 g_RB[N_ * C_];   // normalized reps (B side)
__device__ float g_rowsum[N_];            // sum_j exp(2*sim_ij), diag excluded
__device__ float g_pos[N_];               // LOG2E2 * sim(i, (i+B) mod N)

// ---------------------------------------------------------------- helpers
__device__ __forceinline__ uint32_t smem_u32(const void* p) {
    uint32_t a;
    asm("{ .reg .u64 t; cvta.to.shared.u64 t, %1; cvt.u32.u64 %0, t; }"
        : "=r"(a) : "l"(p));
    return a;
}

__device__ __forceinline__ void ldsm_x4(uint32_t (&r)[4], uint32_t addr) {
    asm volatile("ldmatrix.sync.aligned.m8n8.x4.shared.b16 {%0,%1,%2,%3}, [%4];"
                 : "=r"(r[0]), "=r"(r[1]), "=r"(r[2]), "=r"(r[3]) : "r"(addr));
}

__device__ __forceinline__ void mma16816(float (&d)[4], const uint32_t* a,
                                         uint32_t b0, uint32_t b1) {
    asm volatile(
        "mma.sync.aligned.m16n8k16.row.col.f32.bf16.bf16.f32 "
        "{%0,%1,%2,%3}, {%4,%5,%6,%7}, {%8,%9}, {%0,%1,%2,%3};"
        : "+f"(d[0]), "+f"(d[1]), "+f"(d[2]), "+f"(d[3])
        : "r"(a[0]), "r"(a[1]), "r"(a[2]), "r"(a[3]), "r"(b0), "r"(b1));
}

__device__ __forceinline__ float ex2(float x) {
    float r;
    asm("ex2.approx.f32 %0, %1;" : "=f"(r) : "f"(x));
    return r;
}

#define CP_ASYNC16(saddr, gptr) \
    asm volatile("cp.async.cg.shared.global [%0], [%1], 16;" \
                 :: "r"(saddr), "l"(gptr))
#define CP_COMMIT()  asm volatile("cp.async.commit_group;" ::: "memory")
#define CP_WAIT0()   asm volatile("cp.async.wait_group 0;" ::: "memory")

// ---------------------------------------------------------------- kernel 1
__global__ void __launch_bounds__(256) normalize_kernel(
    const float* __restrict__ zi, const float* __restrict__ zj)
{
    const int w = threadIdx.x >> 5, lane = threadIdx.x & 31;
    const int row = blockIdx.x * 8 + w;
    const float* src = (row < B_) ? (zi + (size_t)row * C_)
                                  : (zj + (size_t)(row - B_) * C_);
    float4 v = ((const float4*)src)[lane];
    float ss = v.x * v.x + v.y * v.y + v.z * v.z + v.w * v.w;
    #pragma unroll
    for (int o = 16; o; o >>= 1) ss += __shfl_xor_sync(0xffffffffu, ss, o);
    const float rn  = rsqrtf(ss);
    const float rnA = rn * LOG2E2;

    __nv_bfloat162 b0 = __floats2bfloat162_rn(v.x * rn, v.y * rn);
    __nv_bfloat162 b1 = __floats2bfloat162_rn(v.z * rn, v.w * rn);
    uint2 pb = { *(uint32_t*)&b0, *(uint32_t*)&b1 };
    ((uint2*)(g_RB + (size_t)row * C_))[lane] = pb;

    __nv_bfloat162 a0 = __floats2bfloat162_rn(v.x * rnA, v.y * rnA);
    __nv_bfloat162 a1 = __floats2bfloat162_rn(v.z * rnA, v.w * rnA);
    uint2 pa = { *(uint32_t*)&a0, *(uint32_t*)&a1 };
    ((uint2*)(g_RA + (size_t)row * C_))[lane] = pa;

    if (blockIdx.x < 32) g_rowsum[blockIdx.x * 256 + threadIdx.x] = 0.f;
}

// ---------------------------------------------------------------- kernel 2
// Symmetric, pipelined, BALANCED: 148 CTAs (1/SM), each owns a contiguous
// range of 14-15 triangle tiles in row-major triangle order. A-stripe
// fragments persist in registers; on stripe change (rare) the CTA flushes
// row sums and reloads A. B tiles double-buffered via cp.async.
extern "C" __global__ void __launch_bounds__(THREADS, 1) ntxent_sym_kernel()
{
    extern __shared__ char smraw[];
    const uint32_t sA32 = smem_u32(smraw);
    const uint32_t sB32 = sA32 + MT * PITCH;

    const int tid  = threadIdx.x;
    const int lane = tid & 31, w = tid >> 5;
    const int wm = w & 3, wn = w >> 2;               // 4 x 4 warp grid

    // contiguous balanced tile range for this CTA
    const int qs = (int)(( (long)blockIdx.x      * NTILE) / NCTA);
    const int qe = (int)(( (long)(blockIdx.x + 1) * NTILE) / NCTA);

    // decode qs -> (I, J)
    int q = qs, I = 0;
    while (q >= NSTRIPE - I) { q -= NSTRIPE - I; I++; }
    int J = I + q;

    // lane geometry
    const int lrow = lane & 15;
    const int lkb  = (lane >> 4) * 16;
    const uint32_t aAddr = sA32 + (uint32_t)((wm * 32 + lrow) * PITCH + lkb);
    const uint32_t bOffs = (uint32_t)((wn * 32 + lrow) * PITCH + lkb);
    const int rquad = lane >> 2;
    const int cpair = (lane & 3) * 2;
    const int cm = tid >> 4, cq = tid & 15;          // copy slots

    // prologue: A stripe(I) + B tile(J)
    #pragma unroll
    for (int p = 0; p < 4; p++) {
        const int m = p * 32 + cm;
        CP_ASYNC16(sA32 + (uint32_t)(m * PITCH + cq * 16),
                   g_RA + (size_t)(I * MT + m) * C_ + cq * 8);
        CP_ASYNC16(sB32 + (uint32_t)(m * PITCH + cq * 16),
                   g_RB + (size_t)(J * MT + m) * C_ + cq * 8);
    }
    CP_COMMIT();
    CP_WAIT0();
    __syncthreads();

    uint32_t aReg[8][2][4];
    #pragma unroll
    for (int ks = 0; ks < 8; ks++) {
        ldsm_x4(aReg[ks][0], aAddr + (uint32_t)(ks * 32));
        ldsm_x4(aReg[ks][1], aAddr + (uint32_t)(16 * PITCH + ks * 32));
    }

    int iw = I * MT + wm * 32;
    float rs[4] = {0.f, 0.f, 0.f, 0.f};             // row sums for stripe I

    for (int t = 0; t < qe - qs; t++) {
        const uint32_t bufR = sB32 + (uint32_t)((t & 1) * (MT * PITCH));

        // next tile coordinates (row-major triangle order)
        const bool haveNext = (t + 1 < qe - qs);
        int In = I, Jn = J + 1;
        if (Jn == NSTRIPE) { In = I + 1; Jn = In; }

        // prefetch next B tile under this tile's compute
        if (haveNext) {
            const uint32_t bufW = sB32 + (uint32_t)(((t + 1) & 1) * (MT * PITCH));
            #pragma unroll
            for (int p = 0; p < 4; p++) {
                const int m = p * 32 + cm;
                CP_ASYNC16(bufW + (uint32_t)(m * PITCH + cq * 16),
                           g_RB + (size_t)(Jn * MT + m) * C_ + cq * 8);
            }
            CP_COMMIT();
        }

        float acc[2][4][4];
        #pragma unroll
        for (int mf = 0; mf < 2; mf++)
            #pragma unroll
            for (int nf = 0; nf < 4; nf++)
                #pragma unroll
                for (int e = 0; e < 4; e++) acc[mf][nf][e] = 0.f;

        #pragma unroll
        for (int ks = 0; ks < 8; ks++) {
            uint32_t b[2][4];
            ldsm_x4(b[0], bufR + bOffs + (uint32_t)(ks * 32));
            ldsm_x4(b[1], bufR + bOffs + (uint32_t)(16 * PITCH + ks * 32));
            #pragma unroll
            for (int mf = 0; mf < 2; mf++)
                #pragma unroll
                for (int nf = 0; nf < 4; nf++) {
                    const int n16 = nf >> 1, g = nf & 1;
                    mma16816(acc[mf][nf], aReg[ks][mf], b[n16][g], b[n16][g + 2]);
                }
        }

        // epilogue: exp once, feed row-side (i) and column-side (j) sums
        const bool diag = (J == I);
        const bool posT = (J == I + 32);
        const bool special = (diag || posT) && (wm == wn);
        const int jt = J * MT + wn * 32;

        float cs[4][2] = {{0.f,0.f},{0.f,0.f},{0.f,0.f},{0.f,0.f}};

        #pragma unroll
        for (int nf = 0; nf < 4; nf++) {
            if (!special) {
                #pragma unroll
                for (int mf = 0; mf < 2; mf++)
                    #pragma unroll
                    for (int e = 0; e < 4; e++) {
                        const float ex = ex2(acc[mf][nf][e]);
                        rs[mf * 2 + (e >> 1)] += ex;
                        cs[nf][e & 1] += ex;
                    }
            } else {
                const int jb = jt + nf * 8;
                #pragma unroll
                for (int mf = 0; mf < 2; mf++)
                    #pragma unroll
                    for (int e = 0; e < 4; e++) {
                        const int ie = iw + mf * 16 + rquad + ((e & 2) ? 8 : 0);
                        const int je = jb + cpair + (e & 1);
                        const float d = acc[mf][nf][e];
                        if (posT && je == ie + B_) { g_pos[ie] = d; g_pos[je] = d; }
                        const float ex = (diag && je == ie) ? 0.f : ex2(d);
                        rs[mf * 2 + (e >> 1)] += ex;
                        cs[nf][e & 1] += ex;
                    }
            }
        }

        // column-side (off-diagonal only): reduce across rquad, atomics
        if (!diag) {
            #pragma unroll
            for (int nf = 0; nf < 4; nf++)
                #pragma unroll
                for (int par = 0; par < 2; par++) {
                    float v = cs[nf][par];
                    v += __shfl_xor_sync(0xffffffffu, v, 4);
                    v += __shfl_xor_sync(0xffffffffu, v, 8);
                    v += __shfl_xor_sync(0xffffffffu, v, 16);
                    if (lane < 4)
                        atomicAdd(&g_rowsum[jt + nf * 8 + cpair + par], v);
                }
        }

        // stripe change (rare): flush row sums, reload A stripe + fragments
        if (haveNext && In != I) {
            #pragma unroll
            for (int p = 0; p < 4; p++) {
                rs[p] += __shfl_xor_sync(0xffffffffu, rs[p], 1);
                rs[p] += __shfl_xor_sync(0xffffffffu, rs[p], 2);
            }
            if ((lane & 3) == 0) {
                #pragma unroll
                for (int p = 0; p < 4; p++)
                    atomicAdd(&g_rowsum[iw + rquad + (p & 1) * 8 + (p >> 1) * 16],
                              rs[p]);
            }
            rs[0] = rs[1] = rs[2] = rs[3] = 0.f;

            __syncthreads();   // all warps done with old A smem (ldsm'd at stripe start)
            #pragma unroll
            for (int p = 0; p < 4; p++) {
                const int m = p * 32 + cm;
                CP_ASYNC16(sA32 + (uint32_t)(m * PITCH + cq * 16),
                           g_RA + (size_t)(In * MT + m) * C_ + cq * 8);
            }
            CP_COMMIT();
            CP_WAIT0();        // also drains the pending B prefetch
            __syncthreads();
            #pragma unroll
            for (int ks = 0; ks < 8; ks++) {
                ldsm_x4(aReg[ks][0], aAddr + (uint32_t)(ks * 32));
                ldsm_x4(aReg[ks][1], aAddr + (uint32_t)(16 * PITCH + ks * 32));
            }
            iw = In * MT + wm * 32;
        } else if (haveNext) {
            CP_WAIT0();
            __syncthreads();
        }

        I = In; J = Jn;
    }

    // final row-side flush
    #pragma unroll
    for (int p = 0; p < 4; p++) {
        rs[p] += __shfl_xor_sync(0xffffffffu, rs[p], 1);
        rs[p] += __shfl_xor_sync(0xffffffffu, rs[p], 2);
    }
    if ((lane & 3) == 0) {
        #pragma unroll
        for (int p = 0; p < 4; p++)
            atomicAdd(&g_rowsum[iw + rquad + (p & 1) * 8 + (p >> 1) * 16], rs[p]);
    }
}

// ---------------------------------------------------------------- kernel 3
// loss_i = log(rowsum_i + 2^ps_i) - ps_i*ln2   (ps = LOG2E2*pos)
__global__ void __launch_bounds__(1024) finalize_kernel(float* __restrict__ out)
{
    const int tid = threadIdx.x;
    float s = 0.f;
    #pragma unroll
    for (int r = tid; r < N_; r += 1024) {
        const float ps = g_pos[r];
        s += logf(g_rowsum[r] + ex2(ps)) - ps * LN2;
    }
    #pragma unroll
    for (int o = 16; o; o >>= 1) s += __shfl_xor_sync(0xffffffffu, s, o);
    __shared__ float sw[32];
    if ((tid & 31) == 0) sw[tid >> 5] = s;
    __syncthreads();
    if (tid < 32) {
        float v = sw[tid];
        #pragma unroll
        for (int o = 16; o; o >>= 1) v += __shfl_xor_sync(0xffffffffu, v, o);
        if (tid == 0) out[0] = v * (1.0f / (float)N_);
    }
}

// ---------------------------------------------------------------- launcher
extern "C" void kernel_launch(void* const* d_in, const int* in_sizes, int n_in,
                              void* d_out, int out_size)
{
    const float* zi = (const float*)d_in[0];
    const float* zj = (const float*)d_in[1];
    float* out = (float*)d_out;

    const int smem_bytes = 3 * MT * PITCH;   // A + 2x B buffers = 104448
    cudaFuncSetAttribute(ntxent_sym_kernel,
                         cudaFuncAttributeMaxDynamicSharedMemorySize, smem_bytes);

    normalize_kernel<<<N_ / 8, 256>>>(zi, zj);
    ntxent_sym_kernel<<<NCTA, THREADS, smem_bytes>>>();
    finalize_kernel<<<1, 1024>>>(out);
}

// round 16
// speedup vs baseline: 3.0856x; 1.0795x over previous
#include <cuda_runtime.h>
#include <cuda_bf16.h>
#include <math.h>
#include <stdint.h>

// ---------------------------------------------------------------- constants
#define B_      4096
#define N_      8192              // 2B rows
#define C_      128               // feature dim
#define MT      128               // block tile (rows and cols)
#define NSTRIPE 64                // 8192 / 128
#define NTILE   2080              // 64*65/2 upper-triangle block pairs
#define NCTA    148               // one CTA per SM, single wave
#define THREADS 512
#define PITCH   272               // smem row pitch (256B bf16 data + 16B pad)
#define BUFSZ   (MT * PITCH)      // 34816 bytes per B buffer
#define DEPTH   4                 // B ring depth
#define LOG2E2  2.8853900817779268f   // 2*log2(e)
#define LN2     0.6931471805599453f

// scratch (__device__ globals: allocation-free)
__device__ __nv_bfloat16 g_RA[N_ * C_];   // normalized reps * LOG2E2 (A side)
__device__ __nv_bfloat16 g_RB[N_ * C_];   // normalized reps (B side)
__device__ float g_rowsum[N_];            // sum_j exp(2*sim_ij), diag excluded
__device__ float g_pos[N_];               // LOG2E2 * sim(i, (i+B) mod N)

// ---------------------------------------------------------------- helpers
__device__ __forceinline__ uint32_t smem_u32(const void* p) {
    uint32_t a;
    asm("{ .reg .u64 t; cvta.to.shared.u64 t, %1; cvt.u32.u64 %0, t; }"
        : "=r"(a) : "l"(p));
    return a;
}

__device__ __forceinline__ void ldsm_x4(uint32_t (&r)[4], uint32_t addr) {
    asm volatile("ldmatrix.sync.aligned.m8n8.x4.shared.b16 {%0,%1,%2,%3}, [%4];"
                 : "=r"(r[0]), "=r"(r[1]), "=r"(r[2]), "=r"(r[3]) : "r"(addr));
}

__device__ __forceinline__ void mma16816(float (&d)[4], const uint32_t* a,
                                         uint32_t b0, uint32_t b1) {
    asm volatile(
        "mma.sync.aligned.m16n8k16.row.col.f32.bf16.bf16.f32 "
        "{%0,%1,%2,%3}, {%4,%5,%6,%7}, {%8,%9}, {%0,%1,%2,%3};"
        : "+f"(d[0]), "+f"(d[1]), "+f"(d[2]), "+f"(d[3])
        : "r"(a[0]), "r"(a[1]), "r"(a[2]), "r"(a[3]), "r"(b0), "r"(b1));
}

__device__ __forceinline__ float ex2(float x) {
    float r;
    asm("ex2.approx.f32 %0, %1;" : "=f"(r) : "f"(x));
    return r;
}

#define CP_ASYNC16(saddr, gptr) \
    asm volatile("cp.async.cg.shared.global [%0], [%1], 16;" \
                 :: "r"(saddr), "l"(gptr))
#define CP_COMMIT()  asm volatile("cp.async.commit_group;" ::: "memory")
#define CP_WAIT0()   asm volatile("cp.async.wait_group 0;" ::: "memory")
#define CP_MBAR_ARRIVE(mb) \
    asm volatile("cp.async.mbarrier.arrive.noinc.shared.b64 [%0];" \
                 :: "r"(mb) : "memory")

#define MBAR_INIT(mb, cnt) \
    asm volatile("mbarrier.init.shared.b64 [%0], %1;" :: "r"(mb), "r"(cnt) : "memory")
#define MBAR_ARRIVE(mb) \
    asm volatile("mbarrier.arrive.shared.b64 _, [%0];" :: "r"(mb) : "memory")

#define MBAR_WAIT_PARITY(mb, ph) do {                                          \
    uint32_t _m = (mb), _p = (ph), _d;                                         \
    asm volatile("{\n .reg .pred p;\n"                                         \
        " mbarrier.try_wait.parity.acquire.cta.shared::cta.b64 p, [%1], %2;\n" \
        " selp.b32 %0, 1, 0, p;\n}"                                            \
        : "=r"(_d) : "r"(_m), "r"(_p) : "memory");                             \
    if (!_d) {                                                                 \
        asm volatile("{\n .reg .pred P1;\n"                                    \
            "WL_%=:\n"                                                         \
            " mbarrier.try_wait.parity.acquire.cta.shared::cta.b64 P1, [%0], %1, 0x989680;\n" \
            " @P1 bra.uni WD_%=;\n bra.uni WL_%=;\nWD_%=:\n}"                  \
            :: "r"(_m), "r"(_p) : "memory");                                   \
    }                                                                          \
} while (0)

// ---------------------------------------------------------------- kernel 1
__global__ void __launch_bounds__(256) normalize_kernel(
    const float* __restrict__ zi, const float* __restrict__ zj)
{
    const int w = threadIdx.x >> 5, lane = threadIdx.x & 31;
    const int row = blockIdx.x * 8 + w;
    const float* src = (row < B_) ? (zi + (size_t)row * C_)
                                  : (zj + (size_t)(row - B_) * C_);
    float4 v = ((const float4*)src)[lane];
    float ss = v.x * v.x + v.y * v.y + v.z * v.z + v.w * v.w;
    #pragma unroll
    for (int o = 16; o; o >>= 1) ss += __shfl_xor_sync(0xffffffffu, ss, o);
    const float rn  = rsqrtf(ss);
    const float rnA = rn * LOG2E2;

    __nv_bfloat162 b0 = __floats2bfloat162_rn(v.x * rn, v.y * rn);
    __nv_bfloat162 b1 = __floats2bfloat162_rn(v.z * rn, v.w * rn);
    uint2 pb = { *(uint32_t*)&b0, *(uint32_t*)&b1 };
    ((uint2*)(g_RB + (size_t)row * C_))[lane] = pb;

    __nv_bfloat162 a0 = __floats2bfloat162_rn(v.x * rnA, v.y * rnA);
    __nv_bfloat162 a1 = __floats2bfloat162_rn(v.z * rnA, v.w * rnA);
    uint2 pa = { *(uint32_t*)&a0, *(uint32_t*)&a1 };
    ((uint2*)(g_RA + (size_t)row * C_))[lane] = pa;

    if (blockIdx.x < 32) g_rowsum[blockIdx.x * 256 + threadIdx.x] = 0.f;
}

// ---------------------------------------------------------------- kernel 2
// Symmetric, balanced (148 CTAs), mbarrier-ring pipelined (DEPTH=4):
// warps drift across tile phases so epilogue(t) overlaps MMA(t+1..t+3)
// on the tensor pipe. A-stripe fragments persist in registers.
extern "C" __global__ void __launch_bounds__(THREADS, 1) ntxent_sym_kernel()
{
    extern __shared__ char smraw[];
    const uint32_t sbase = smem_u32(smraw);
    const uint32_t FULLB = sbase;            // 4 x 8B
    const uint32_t EMPTB = sbase + 32;       // 4 x 8B
    const uint32_t sA32  = sbase + 1024;
    const uint32_t sB32  = sA32 + BUFSZ;     // ring of DEPTH buffers

    const int tid  = threadIdx.x;
    const int lane = tid & 31, w = tid >> 5;
    const int wm = w & 3, wn = w >> 2;               // 4 x 4 warp grid

    // balanced contiguous tile range
    const int qs = (int)(((long)blockIdx.x       * NTILE) / NCTA);
    const int qe = (int)(((long)(blockIdx.x + 1) * NTILE) / NCTA);
    const int nt = qe - qs;

    // decode qs -> (I, J); producer copy
    int q = qs, I = 0;
    while (q >= NSTRIPE - I) { q -= NSTRIPE - I; I++; }
    int J = I + q;
    int Ip = I, Jp = J;

    // lane geometry
    const int lrow = lane & 15;
    const int lkb  = (lane >> 4) * 16;
    const uint32_t aAddr = sA32 + (uint32_t)((wm * 32 + lrow) * PITCH + lkb);
    const uint32_t bOffs = (uint32_t)((wn * 32 + lrow) * PITCH + lkb);
    const int rquad = lane >> 2;
    const int cpair = (lane & 3) * 2;
    const int cm = tid >> 4, cq = tid & 15;          // copy slots

    // init mbarriers
    if (tid == 0) {
        #pragma unroll
        for (int s = 0; s < DEPTH; s++) {
            MBAR_INIT(FULLB + s * 8, THREADS);
            MBAR_INIT(EMPTB + s * 8, THREADS);
        }
    }
    __syncthreads();

    // A stripe prologue (own commit group)
    #pragma unroll
    for (int p = 0; p < 4; p++) {
        const int m = p * 32 + cm;
        CP_ASYNC16(sA32 + (uint32_t)(m * PITCH + cq * 16),
                   g_RA + (size_t)(I * MT + m) * C_ + cq * 8);
    }
    CP_COMMIT();

    // producer prologue: fill up to 3 ring slots
    const int npro = nt < 3 ? nt : 3;
    for (int u = 0; u < npro; u++) {
        const uint32_t bufW = sB32 + (uint32_t)(u * BUFSZ);
        #pragma unroll
        for (int p = 0; p < 4; p++) {
            const int m = p * 32 + cm;
            CP_ASYNC16(bufW + (uint32_t)(m * PITCH + cq * 16),
                       g_RB + (size_t)(Jp * MT + m) * C_ + cq * 8);
        }
        CP_MBAR_ARRIVE(FULLB + u * 8);
        Jp++; if (Jp == NSTRIPE) { Ip++; Jp = Ip; }
    }

    // wait for A, load persistent fragments
    CP_WAIT0();          // drains the committed A group (B tracked by mbarriers)
    __syncthreads();
    uint32_t aReg[8][2][4];
    #pragma unroll
    for (int ks = 0; ks < 8; ks++) {
        ldsm_x4(aReg[ks][0], aAddr + (uint32_t)(ks * 32));
        ldsm_x4(aReg[ks][1], aAddr + (uint32_t)(16 * PITCH + ks * 32));
    }

    int iw = I * MT + wm * 32;
    float rs[4] = {0.f, 0.f, 0.f, 0.f};

    for (int t = 0; t < nt; t++) {
        const int slot = t & (DEPTH - 1);
        const uint32_t bufR = sB32 + (uint32_t)(slot * BUFSZ);

        // consume: wait full, MMA, release
        MBAR_WAIT_PARITY(FULLB + slot * 8, (t >> 2) & 1);

        float acc[2][4][4];
        #pragma unroll
        for (int mf = 0; mf < 2; mf++)
            #pragma unroll
            for (int nf = 0; nf < 4; nf++)
                #pragma unroll
                for (int e = 0; e < 4; e++) acc[mf][nf][e] = 0.f;

        #pragma unroll
        for (int ks = 0; ks < 8; ks++) {
            uint32_t b[2][4];
            ldsm_x4(b[0], bufR + bOffs + (uint32_t)(ks * 32));
            ldsm_x4(b[1], bufR + bOffs + (uint32_t)(16 * PITCH + ks * 32));
            #pragma unroll
            for (int mf = 0; mf < 2; mf++)
                #pragma unroll
                for (int nf = 0; nf < 4; nf++) {
                    const int n16 = nf >> 1, g = nf & 1;
                    mma16816(acc[mf][nf], aReg[ks][mf], b[n16][g], b[n16][g + 2]);
                }
        }
        MBAR_ARRIVE(EMPTB + slot * 8);       // fragments consumed by MMA

        // epilogue: exp once, feed row-side (i) and column-side (j) sums
        const bool diag = (J == I);
        const bool posT = (J == I + 32);
        const bool special = (diag || posT) && (wm == wn);
        const int jt = J * MT + wn * 32;

        float cs[4][2] = {{0.f,0.f},{0.f,0.f},{0.f,0.f},{0.f,0.f}};

        #pragma unroll
        for (int nf = 0; nf < 4; nf++) {
            if (!special) {
                #pragma unroll
                for (int mf = 0; mf < 2; mf++)
                    #pragma unroll
                    for (int e = 0; e < 4; e++) {
                        const float ex = ex2(acc[mf][nf][e]);
                        rs[mf * 2 + (e >> 1)] += ex;
                        cs[nf][e & 1] += ex;
                    }
            } else {
                const int jb = jt + nf * 8;
                #pragma unroll
                for (int mf = 0; mf < 2; mf++)
                    #pragma unroll
                    for (int e = 0; e < 4; e++) {
                        const int ie = iw + mf * 16 + rquad + ((e & 2) ? 8 : 0);
                        const int je = jb + cpair + (e & 1);
                        const float d = acc[mf][nf][e];
                        if (posT && je == ie + B_) { g_pos[ie] = d; g_pos[je] = d; }
                        const float ex = (diag && je == ie) ? 0.f : ex2(d);
                        rs[mf * 2 + (e >> 1)] += ex;
                        cs[nf][e & 1] += ex;
                    }
            }
        }

        if (!diag) {
            #pragma unroll
            for (int nf = 0; nf < 4; nf++)
                #pragma unroll
                for (int par = 0; par < 2; par++) {
                    float v = cs[nf][par];
                    v += __shfl_xor_sync(0xffffffffu, v, 4);
                    v += __shfl_xor_sync(0xffffffffu, v, 8);
                    v += __shfl_xor_sync(0xffffffffu, v, 16);
                    if (lane < 4)
                        atomicAdd(&g_rowsum[jt + nf * 8 + cpair + par], v);
                }
        }

        // next consumer tile; stripe change reloads A (rare)
        const bool haveNext = (t + 1 < nt);
        int In = I, Jn = J + 1;
        if (Jn == NSTRIPE) { In = I + 1; Jn = In; }

        if (haveNext && In != I) {
            #pragma unroll
            for (int p = 0; p < 4; p++) {
                rs[p] += __shfl_xor_sync(0xffffffffu, rs[p], 1);
                rs[p] += __shfl_xor_sync(0xffffffffu, rs[p], 2);
            }
            if ((lane & 3) == 0) {
                #pragma unroll
                for (int p = 0; p < 4; p++)
                    atomicAdd(&g_rowsum[iw + rquad + (p & 1) * 8 + (p >> 1) * 16],
                              rs[p]);
            }
            rs[0] = rs[1] = rs[2] = rs[3] = 0.f;

            __syncthreads();                 // converge; old A fragments done
            #pragma unroll
            for (int p = 0; p < 4; p++) {
                const int m = p * 32 + cm;
                CP_ASYNC16(sA32 + (uint32_t)(m * PITCH + cq * 16),
                           g_RA + (size_t)(In * MT + m) * C_ + cq * 8);
            }
            CP_COMMIT();
            CP_WAIT0();
            __syncthreads();
            #pragma unroll
            for (int ks = 0; ks < 8; ks++) {
                ldsm_x4(aReg[ks][0], aAddr + (uint32_t)(ks * 32));
                ldsm_x4(aReg[ks][1], aAddr + (uint32_t)(16 * PITCH + ks * 32));
            }
            iw = In * MT + wm * 32;
        }

        // produce tile t+3 into its slot
        if (t + 3 < nt) {
            const int u = t + 3, s2 = u & (DEPTH - 1);
            if (u >= DEPTH)
                MBAR_WAIT_PARITY(EMPTB + s2 * 8, ((u >> 2) & 1) ^ 1);
            const uint32_t bufW = sB32 + (uint32_t)(s2 * BUFSZ);
            #pragma unroll
            for (int p = 0; p < 4; p++) {
                const int m = p * 32 + cm;
                CP_ASYNC16(bufW + (uint32_t)(m * PITCH + cq * 16),
                           g_RB + (size_t)(Jp * MT + m) * C_ + cq * 8);
            }
            CP_MBAR_ARRIVE(FULLB + s2 * 8);
            Jp++; if (Jp == NSTRIPE) { Ip++; Jp = Ip; }
        }

        I = In; J = Jn;
    }

    // final row-side flush
    #pragma unroll
    for (int p = 0; p < 4; p++) {
        rs[p] += __shfl_xor_sync(0xffffffffu, rs[p], 1);
        rs[p] += __shfl_xor_sync(0xffffffffu, rs[p], 2);
    }
    if ((lane & 3) == 0) {
        #pragma unroll
        for (int p = 0; p < 4; p++)
            atomicAdd(&g_rowsum[iw + rquad + (p & 1) * 8 + (p >> 1) * 16], rs[p]);
    }
}

// ---------------------------------------------------------------- kernel 3
__global__ void __launch_bounds__(1024) finalize_kernel(float* __restrict__ out)
{
    const int tid = threadIdx.x;
    float s = 0.f;
    #pragma unroll
    for (int r = tid; r < N_; r += 1024) {
        const float ps = g_pos[r];
        s += logf(g_rowsum[r] + ex2(ps)) - ps * LN2;
    }
    #pragma unroll
    for (int o = 16; o; o >>= 1) s += __shfl_xor_sync(0xffffffffu, s, o);
    __shared__ float sw[32];
    if ((tid & 31) == 0) sw[tid >> 5] = s;
    __syncthreads();
    if (tid < 32) {
        float v = sw[tid];
        #pragma unroll
        for (int o = 16; o; o >>= 1) v += __shfl_xor_sync(0xffffffffu, v, o);
        if (tid == 0) out[0] = v * (1.0f / (float)N_);
    }
}

// ---------------------------------------------------------------- launcher
extern "C" void kernel_launch(void* const* d_in, const int* in_sizes, int n_in,
                              void* d_out, int out_size)
{
    const float* zi = (const float*)d_in[0];
    const float* zj = (const float*)d_in[1];
    float* out = (float*)d_out;

    const int smem_bytes = 1024 + (1 + DEPTH) * BUFSZ;   // 1024 + 5*34816 = 175104
    cudaFuncSetAttribute(ntxent_sym_kernel,
                         cudaFuncAttributeMaxDynamicSharedMemorySize, smem_bytes);

    normalize_kernel<<<N_ / 8, 256>>>(zi, zj);
    ntxent_sym_kernel<<<NCTA, THREADS, smem_bytes>>>();
    finalize_kernel<<<1, 1024>>>(out);
}

// round 17
// speedup vs baseline: 3.3476x; 1.0849x over previous
#include <cuda_runtime.h>
#include <cuda_bf16.h>
#include <math.h>
#include <stdint.h>

// ---------------------------------------------------------------- constants
#define B_      4096
#define N_      8192              // 2B rows
#define C_      128               // feature dim
#define MT      128               // block tile (rows and cols)
#define NSTRIPE 64                // 8192 / 128
#define NTILE   2080              // 64*65/2 upper-triangle block pairs
#define NCTA    148               // one CTA per SM, single wave
#define THREADS 512
#define PITCH   272               // smem row pitch (256B bf16 data + 16B pad)
#define BUFSZ   (MT * PITCH)      // 34816 bytes per buffer
#define DEPTH   4                 // B ring depth
#define ABUF    2                 // A ring depth
#define LOG2E2  2.8853900817779268f   // 2*log2(e)
#define LN2     0.6931471805599453f

// scratch (__device__ globals: allocation-free)
__device__ __nv_bfloat16 g_RA[N_ * C_];   // normalized reps * LOG2E2 (A side)
__device__ __nv_bfloat16 g_RB[N_ * C_];   // normalized reps (B side)
__device__ float g_rowsum[N_];            // sum_j exp(2*sim_ij), diag excluded
__device__ float g_pos[N_];               // LOG2E2 * sim(i, (i+B) mod N)

// ---------------------------------------------------------------- helpers
__device__ __forceinline__ uint32_t smem_u32(const void* p) {
    uint32_t a;
    asm("{ .reg .u64 t; cvta.to.shared.u64 t, %1; cvt.u32.u64 %0, t; }"
        : "=r"(a) : "l"(p));
    return a;
}

__device__ __forceinline__ void ldsm_x4(uint32_t (&r)[4], uint32_t addr) {
    asm volatile("ldmatrix.sync.aligned.m8n8.x4.shared.b16 {%0,%1,%2,%3}, [%4];"
                 : "=r"(r[0]), "=r"(r[1]), "=r"(r[2]), "=r"(r[3]) : "r"(addr));
}

__device__ __forceinline__ void mma16816(float (&d)[4], const uint32_t* a,
                                         uint32_t b0, uint32_t b1) {
    asm volatile(
        "mma.sync.aligned.m16n8k16.row.col.f32.bf16.bf16.f32 "
        "{%0,%1,%2,%3}, {%4,%5,%6,%7}, {%8,%9}, {%0,%1,%2,%3};"
        : "+f"(d[0]), "+f"(d[1]), "+f"(d[2]), "+f"(d[3])
        : "r"(a[0]), "r"(a[1]), "r"(a[2]), "r"(a[3]), "r"(b0), "r"(b1));
}

__device__ __forceinline__ float ex2(float x) {
    float r;
    asm("ex2.approx.f32 %0, %1;" : "=f"(r) : "f"(x));
    return r;
}

#define CP_ASYNC16(saddr, gptr) \
    asm volatile("cp.async.cg.shared.global [%0], [%1], 16;" \
                 :: "r"(saddr), "l"(gptr))
#define CP_MBAR_ARRIVE(mb) \
    asm volatile("cp.async.mbarrier.arrive.noinc.shared.b64 [%0];" \
                 :: "r"(mb) : "memory")

#define MBAR_INIT(mb, cnt) \
    asm volatile("mbarrier.init.shared.b64 [%0], %1;" :: "r"(mb), "r"(cnt) : "memory")
#define MBAR_ARRIVE(mb) \
    asm volatile("mbarrier.arrive.shared.b64 _, [%0];" :: "r"(mb) : "memory")

#define MBAR_WAIT_PARITY(mb, ph) do {                                          \
    uint32_t _m = (mb), _p = (ph), _d;                                         \
    asm volatile("{\n .reg .pred p;\n"                                         \
        " mbarrier.try_wait.parity.acquire.cta.shared::cta.b64 p, [%1], %2;\n" \
        " selp.b32 %0, 1, 0, p;\n}"                                            \
        : "=r"(_d) : "r"(_m), "r"(_p) : "memory");                             \
    if (!_d) {                                                                 \
        asm volatile("{\n .reg .pred P1;\n"                                    \
            "WL_%=:\n"                                                         \
            " mbarrier.try_wait.parity.acquire.cta.shared::cta.b64 P1, [%0], %1, 0x989680;\n" \
            " @P1 bra.uni WD_%=;\n bra.uni WL_%=;\nWD_%=:\n}"                  \
            :: "r"(_m), "r"(_p) : "memory");                                   \
    }                                                                          \
} while (0)

// ---------------------------------------------------------------- kernel 1
__global__ void __launch_bounds__(256) normalize_kernel(
    const float* __restrict__ zi, const float* __restrict__ zj)
{
    const int w = threadIdx.x >> 5, lane = threadIdx.x & 31;
    const int row = blockIdx.x * 8 + w;
    const float* src = (row < B_) ? (zi + (size_t)row * C_)
                                  : (zj + (size_t)(row - B_) * C_);
    float4 v = ((const float4*)src)[lane];
    float ss = v.x * v.x + v.y * v.y + v.z * v.z + v.w * v.w;
    #pragma unroll
    for (int o = 16; o; o >>= 1) ss += __shfl_xor_sync(0xffffffffu, ss, o);
    const float rn  = rsqrtf(ss);
    const float rnA = rn * LOG2E2;

    __nv_bfloat162 b0 = __floats2bfloat162_rn(v.x * rn, v.y * rn);
    __nv_bfloat162 b1 = __floats2bfloat162_rn(v.z * rn, v.w * rn);
    uint2 pb = { *(uint32_t*)&b0, *(uint32_t*)&b1 };
    ((uint2*)(g_RB + (size_t)row * C_))[lane] = pb;

    __nv_bfloat162 a0 = __floats2bfloat162_rn(v.x * rnA, v.y * rnA);
    __nv_bfloat162 a1 = __floats2bfloat162_rn(v.z * rnA, v.w * rnA);
    uint2 pa = { *(uint32_t*)&a0, *(uint32_t*)&a1 };
    ((uint2*)(g_RA + (size_t)row * C_))[lane] = pa;

    if (blockIdx.x < 32) g_rowsum[blockIdx.x * 256 + threadIdx.x] = 0.f;
}

// ---------------------------------------------------------------- kernel 2
// Symmetric, balanced (148 CTAs), fully mbarrier-pipelined:
// B tiles in a depth-4 ring AND A stripes in a depth-2 ring. No syncthreads
// or cp.async drains inside the main loop -- stripe changes are just another
// producer stream, so the tensor pipe never empties.
extern "C" __global__ void __launch_bounds__(THREADS, 1) ntxent_sym_kernel()
{
    extern __shared__ char smraw[];
    const uint32_t sbase  = smem_u32(smraw);
    const uint32_t BFULLB = sbase;            // 4 x 8B
    const uint32_t BEMPTB = sbase + 32;       // 4 x 8B
    const uint32_t AFULLB = sbase + 64;       // 2 x 8B
    const uint32_t AEMPTB = sbase + 96;       // 2 x 8B
    const uint32_t sAring = sbase + 1024;     // 2 buffers
    const uint32_t sBring = sAring + ABUF * BUFSZ;   // 4 buffers

    const int tid  = threadIdx.x;
    const int lane = tid & 31, w = tid >> 5;
    const int wm = w & 3, wn = w >> 2;               // 4 x 4 warp grid

    // balanced contiguous tile range
    const int qs = (int)(((long)blockIdx.x       * NTILE) / NCTA);
    const int qe = (int)(((long)(blockIdx.x + 1) * NTILE) / NCTA);
    const int nt = qe - qs;

    // decode qs -> (I, J)
    int q = qs, I = 0;
    while (q >= NSTRIPE - I) { q -= NSTRIPE - I; I++; }
    int J = I + q;
    const int Istart = I;
    int Ip = I, Jp = J;                              // producer walker

    // lane geometry
    const int lrow = lane & 15;
    const int lkb  = (lane >> 4) * 16;
    const uint32_t aOffs = (uint32_t)((wm * 32 + lrow) * PITCH + lkb);
    const uint32_t bOffs = (uint32_t)((wn * 32 + lrow) * PITCH + lkb);
    const int rquad = lane >> 2;
    const int cpair = (lane & 3) * 2;
    const int cm = tid >> 4, cq = tid & 15;          // copy slots

    if (tid == 0) {
        #pragma unroll
        for (int s = 0; s < DEPTH; s++) {
            MBAR_INIT(BFULLB + s * 8, THREADS);
            MBAR_INIT(BEMPTB + s * 8, THREADS);
        }
        #pragma unroll
        for (int s = 0; s < ABUF; s++) {
            MBAR_INIT(AFULLB + s * 8, THREADS);
            MBAR_INIT(AEMPTB + s * 8, THREADS);
        }
    }
    __syncthreads();

    // producer: issues A stripe (on segment start) + B tile for tile index u
    auto produce = [&](int u, bool newstripe) {
        if (newstripe) {
            const int seg = Ip - Istart;
            const int as  = seg & 1;
            if (seg >= ABUF)
                MBAR_WAIT_PARITY(AEMPTB + as * 8, ((seg >> 1) & 1) ^ 1);
            const uint32_t abuf = sAring + (uint32_t)(as * BUFSZ);
            #pragma unroll
            for (int p = 0; p < 4; p++) {
                const int m = p * 32 + cm;
                CP_ASYNC16(abuf + (uint32_t)(m * PITCH + cq * 16),
                           g_RA + (size_t)(Ip * MT + m) * C_ + cq * 8);
            }
            CP_MBAR_ARRIVE(AFULLB + as * 8);
        }
        const int slot = u & (DEPTH - 1);
        if (u >= DEPTH)
            MBAR_WAIT_PARITY(BEMPTB + slot * 8, ((u >> 2) & 1) ^ 1);
        const uint32_t bufW = sBring + (uint32_t)(slot * BUFSZ);
        #pragma unroll
        for (int p = 0; p < 4; p++) {
            const int m = p * 32 + cm;
            CP_ASYNC16(bufW + (uint32_t)(m * PITCH + cq * 16),
                       g_RB + (size_t)(Jp * MT + m) * C_ + cq * 8);
        }
        CP_MBAR_ARRIVE(BFULLB + slot * 8);
        // advance producer walker
        Jp++; if (Jp == NSTRIPE) { Ip++; Jp = Ip; }
    };

    // prologue: fill up to 3 B slots (A segment 0 rides along with u==0)
    const int npro = nt < 3 ? nt : 3;
    for (int u = 0; u < npro; u++) {
        const bool ns = (u == 0) || (Jp == Ip);      // first tile of a stripe
        produce(u, ns);
    }

    uint32_t aReg[8][2][4];
    int iw = 0;
    int segC = -1;                                   // consumer segment
    float rs[4] = {0.f, 0.f, 0.f, 0.f};

    for (int t = 0; t < nt; t++) {
        // stripe entry: flush old rows, swap in new A fragments (no syncs)
        if (t == 0 || J == I) {
            const int seg = I - Istart;
            if (t > 0) {
                #pragma unroll
                for (int p = 0; p < 4; p++) {
                    rs[p] += __shfl_xor_sync(0xffffffffu, rs[p], 1);
                    rs[p] += __shfl_xor_sync(0xffffffffu, rs[p], 2);
                }
                if ((lane & 3) == 0) {
                    #pragma unroll
                    for (int p = 0; p < 4; p++)
                        atomicAdd(&g_rowsum[iw + rquad + (p & 1) * 8 + (p >> 1) * 16],
                                  rs[p]);
                }
                rs[0] = rs[1] = rs[2] = rs[3] = 0.f;
            }
            const int as = seg & 1;
            MBAR_WAIT_PARITY(AFULLB + as * 8, (seg >> 1) & 1);
            const uint32_t abuf = sAring + (uint32_t)(as * BUFSZ) + aOffs;
            #pragma unroll
            for (int ks = 0; ks < 8; ks++) {
                ldsm_x4(aReg[ks][0], abuf + (uint32_t)(ks * 32));
                ldsm_x4(aReg[ks][1], abuf + (uint32_t)(16 * PITCH + ks * 32));
            }
            MBAR_ARRIVE(AEMPTB + as * 8);
            iw = I * MT + wm * 32;
            segC = seg;
        }

        const int slot = t & (DEPTH - 1);
        const uint32_t bufR = sBring + (uint32_t)(slot * BUFSZ);

        MBAR_WAIT_PARITY(BFULLB + slot * 8, (t >> 2) & 1);

        float acc[2][4][4];
        #pragma unroll
        for (int mf = 0; mf < 2; mf++)
            #pragma unroll
            for (int nf = 0; nf < 4; nf++)
                #pragma unroll
                for (int e = 0; e < 4; e++) acc[mf][nf][e] = 0.f;

        #pragma unroll
        for (int ks = 0; ks < 8; ks++) {
            uint32_t b[2][4];
            ldsm_x4(b[0], bufR + bOffs + (uint32_t)(ks * 32));
            ldsm_x4(b[1], bufR + bOffs + (uint32_t)(16 * PITCH + ks * 32));
            #pragma unroll
            for (int mf = 0; mf < 2; mf++)
                #pragma unroll
                for (int nf = 0; nf < 4; nf++) {
                    const int n16 = nf >> 1, g = nf & 1;
                    mma16816(acc[mf][nf], aReg[ks][mf], b[n16][g], b[n16][g + 2]);
                }
        }
        MBAR_ARRIVE(BEMPTB + slot * 8);

        // epilogue: exp once, feed row-side (i) and column-side (j) sums
        const bool diag = (J == I);
        const bool posT = (J == I + 32);
        const bool special = (diag || posT) && (wm == wn);
        const int jt = J * MT + wn * 32;

        float cs[4][2] = {{0.f,0.f},{0.f,0.f},{0.f,0.f},{0.f,0.f}};

        #pragma unroll
        for (int nf = 0; nf < 4; nf++) {
            if (!special) {
                #pragma unroll
                for (int mf = 0; mf < 2; mf++)
                    #pragma unroll
                    for (int e = 0; e < 4; e++) {
                        const float ex = ex2(acc[mf][nf][e]);
                        rs[mf * 2 + (e >> 1)] += ex;
                        cs[nf][e & 1] += ex;
                    }
            } else {
                const int jb = jt + nf * 8;
                #pragma unroll
                for (int mf = 0; mf < 2; mf++)
                    #pragma unroll
                    for (int e = 0; e < 4; e++) {
                        const int ie = iw + mf * 16 + rquad + ((e & 2) ? 8 : 0);
                        const int je = jb + cpair + (e & 1);
                        const float d = acc[mf][nf][e];
                        if (posT && je == ie + B_) { g_pos[ie] = d; g_pos[je] = d; }
                        const float ex = (diag && je == ie) ? 0.f : ex2(d);
                        rs[mf * 2 + (e >> 1)] += ex;
                        cs[nf][e & 1] += ex;
                    }
            }
        }

        if (!diag) {
            #pragma unroll
            for (int nf = 0; nf < 4; nf++)
                #pragma unroll
                for (int par = 0; par < 2; par++) {
                    float v = cs[nf][par];
                    v += __shfl_xor_sync(0xffffffffu, v, 4);
                    v += __shfl_xor_sync(0xffffffffu, v, 8);
                    v += __shfl_xor_sync(0xffffffffu, v, 16);
                    if (lane < 4)
                        atomicAdd(&g_rowsum[jt + nf * 8 + cpair + par], v);
                }
        }

        // produce tile t+3 (A stripe prefetch rides along at boundaries)
        if (t + 3 < nt) {
            const bool ns = (Jp == Ip);              // next produced tile opens a stripe
            produce(t + 3, ns);
        }

        // advance consumer walker
        J++; if (J == NSTRIPE) { I++; J = I; }
    }

    // final row-side flush
    #pragma unroll
    for (int p = 0; p < 4; p++) {
        rs[p] += __shfl_xor_sync(0xffffffffu, rs[p], 1);
        rs[p] += __shfl_xor_sync(0xffffffffu, rs[p], 2);
    }
    if ((lane & 3) == 0) {
        #pragma unroll
        for (int p = 0; p < 4; p++)
            atomicAdd(&g_rowsum[iw + rquad + (p & 1) * 8 + (p >> 1) * 16], rs[p]);
    }
}

// ---------------------------------------------------------------- kernel 3
__global__ void __launch_bounds__(1024) finalize_kernel(float* __restrict__ out)
{
    const int tid = threadIdx.x;
    float s = 0.f;
    #pragma unroll
    for (int r = tid; r < N_; r += 1024) {
        const float ps = g_pos[r];
        s += logf(g_rowsum[r] + ex2(ps)) - ps * LN2;
    }
    #pragma unroll
    for (int o = 16; o; o >>= 1) s += __shfl_xor_sync(0xffffffffu, s, o);
    __shared__ float sw[32];
    if ((tid & 31) == 0) sw[tid >> 5] = s;
    __syncthreads();
    if (tid < 32) {
        float v = sw[tid];
        #pragma unroll
        for (int o = 16; o; o >>= 1) v += __shfl_xor_sync(0xffffffffu, v, o);
        if (tid == 0) out[0] = v * (1.0f / (float)N_);
    }
}

// ---------------------------------------------------------------- launcher
extern "C" void kernel_launch(void* const* d_in, const int* in_sizes, int n_in,
                              void* d_out, int out_size)
{
    const float* zi = (const float*)d_in[0];
    const float* zj = (const float*)d_in[1];
    float* out = (float*)d_out;

    const int smem_bytes = 1024 + (ABUF + DEPTH) * BUFSZ;  // 1024 + 6*34816 = 209920
    cudaFuncSetAttribute(ntxent_sym_kernel,
                         cudaFuncAttributeMaxDynamicSharedMemorySize, smem_bytes);

    normalize_kernel<<<N_ / 8, 256>>>(zi, zj);
    ntxent_sym_kernel<<<NCTA, THREADS, smem_bytes>>>();
    finalize_kernel<<<1, 1024>>>(out);
}